// round 3
// baseline (speedup 1.0000x reference)
#include <cuda_runtime.h>
#include <cuda_fp16.h>
#include <cstdint>

#define HW    512
#define NPIX  (HW * HW)          // 262144
#define NC    64
#define CAP   16                 // bucket capacity (Poisson(1): overflow prob ~0)

// Scratch (__device__ globals per allocation-free rule)
__device__ __half g_refT[(size_t)NPIX * NC];       // ref transposed (pix, C), fp16: 32 MB
__device__ int    g_cnt[NPIX];                     // bucket counts for inverse nnf_rs
__device__ int    g_bucket[(size_t)NPIX * CAP];    // bucket entries: ref-pixel index r

// ---------------------------------------------------------------------------
// 1) Transpose + downconvert: ref (C,H,W) fp32 -> refT (H*W, C) fp16.
// ---------------------------------------------------------------------------
__global__ __launch_bounds__(256) void transpose_ref_kernel(const float* __restrict__ ref) {
    __shared__ float tile[64][65];
    const int pixBase = blockIdx.x * 64;
    const int tx = threadIdx.x;   // 0..63
    const int ty = threadIdx.y;   // 0..3

    #pragma unroll
    for (int c = ty; c < NC; c += 4)
        tile[c][tx] = ref[(size_t)c * NPIX + pixBase + tx];   // coalesced over pixels
    __syncthreads();
    #pragma unroll
    for (int p = ty; p < 64; p += 4)
        g_refT[(size_t)(pixBase + p) * NC + tx] = __float2half(tile[tx][p]);
}

// ---------------------------------------------------------------------------
// 2a) Zero bucket counts.
// ---------------------------------------------------------------------------
__global__ __launch_bounds__(256) void zero_cnt_kernel() {
    const int i = blockIdx.x * blockDim.x + threadIdx.x;
    if (i < NPIX) g_cnt[i] = 0;
}

// 2b) Invert nnf_rs: bucket ref pixels r by their target s = nnf_rs[r].
__global__ __launch_bounds__(256) void build_buckets_kernel(const int* __restrict__ nnf_rs) {
    const int r = blockIdx.x * blockDim.x + threadIdx.x;
    if (r >= NPIX) return;
    const int2 nn = ((const int2*)nnf_rs)[r];     // (sy, sx), guaranteed in [0,512)
    const int key = nn.x * HW + nn.y;
    const int slot = atomicAdd(&g_cnt[key], 1);
    if (slot < CAP) g_bucket[(size_t)key * CAP + slot] = r;
}

// ---------------------------------------------------------------------------
// 3) Fused vote: one warp per output pixel. Both passes as gathers, inline
//    normalize, direct coalesced write to out (C,H,W) via smem staging.
//    Pass1 tap d: source s = t-d, ref coord q = nnf_sr[s]+d.
//    Pass2 tap d: bucket key b = t-d (same index!), entries r, q = r+d.
// ---------------------------------------------------------------------------
__global__ __launch_bounds__(512) void vote_kernel(const int* __restrict__ nnf_sr,
                                                   float* __restrict__ out) {
    __shared__ float s_out[16][65];
    const int warp = threadIdx.x >> 5;            // 0..15 -> pixel within block
    const int lane = threadIdx.x & 31;            // channel pair
    const int pixBase = blockIdx.x * 16;          // 16 consecutive x-pixels (no row cross)
    const int t  = pixBase + warp;
    const int ty = t >> 9;
    const int tx = t & (HW - 1);

    float2 a1 = make_float2(0.f, 0.f);            // pass1 sum
    float2 a2 = make_float2(0.f, 0.f);            // pass2 sum
    int c1 = 0, c2 = 0;

    #pragma unroll
    for (int dy = -1; dy <= 1; dy++) {
        #pragma unroll
        for (int dx = -1; dx <= 1; dx++) {
            const int sy = ty - dy, sx = tx - dx;
            if ((unsigned)sy < HW && (unsigned)sx < HW) {
                const int sidx = sy * HW + sx;

                // ---- pass 1 (src->ref vote, gather form) ----
                const int2 nn = __ldg(&((const int2*)nnf_sr)[sidx]);
                const int qy = nn.x + dy, qx = nn.y + dx;
                if ((unsigned)qy < HW && (unsigned)qx < HW) {
                    const __half2 h = __ldg(
                        &((const __half2*)(g_refT + (size_t)(qy * HW + qx) * NC))[lane]);
                    const float2 v = __half22float2(h);
                    a1.x += v.x; a1.y += v.y; c1++;
                }

                // ---- pass 2 (ref->src vote, via inverse buckets) ----
                int n = g_cnt[sidx];
                if (n > CAP) n = CAP;
                const int* bk = g_bucket + (size_t)sidx * CAP;
                for (int i = 0; i < n; i++) {
                    const int r = bk[i];                      // broadcast load
                    const int ry = r >> 9, rx = r & (HW - 1);
                    const int q2y = ry + dy, q2x = rx + dx;
                    if ((unsigned)q2y < HW && (unsigned)q2x < HW) {
                        const __half2 h = __ldg(
                            &((const __half2*)(g_refT + (size_t)(q2y * HW + q2x) * NC))[lane]);
                        const float2 v = __half22float2(h);
                        a2.x += v.x; a2.y += v.y; c2++;
                    }
                }
            }
        }
    }

    const float ws = 1.0f / (float)NPIX;
    const float wr = 2.0f / (float)NPIX;
    const float w  = ws * (float)c1 + wr * (float)c2;
    const float inv = (w == 0.f) ? 1.f : (1.f / w);   // w>0 always (center tap), keep guard
    s_out[warp][2 * lane]     = (ws * a1.x + wr * a2.x) * inv;
    s_out[warp][2 * lane + 1] = (ws * a1.y + wr * a2.y) * inv;
    __syncthreads();

    // Transposed writeout: 512 threads cover 16 pix x 64 ch.
    const int p = threadIdx.x & 15;
    const int c = threadIdx.x >> 4;                   // 0..31
    out[(size_t)c        * NPIX + pixBase + p] = s_out[p][c];
    out[(size_t)(c + 32) * NPIX + pixBase + p] = s_out[p][c + 32];
}

// ---------------------------------------------------------------------------
extern "C" void kernel_launch(void* const* d_in, const int* in_sizes, int n_in,
                              void* d_out, int out_size) {
    const float* ref    = (const float*)d_in[0];
    const int*   nnf_sr = (const int*)d_in[1];
    const int*   nnf_rs = (const int*)d_in[2];
    float*       out    = (float*)d_out;

    dim3 t2d(64, 4);
    transpose_ref_kernel<<<NPIX / 64, t2d>>>(ref);
    zero_cnt_kernel<<<NPIX / 256, 256>>>();
    build_buckets_kernel<<<NPIX / 256, 256>>>(nnf_rs);
    vote_kernel<<<NPIX / 16, 512>>>(nnf_sr, out);
}

// round 4
// speedup vs baseline: 1.9076x; 1.9076x over previous
#include <cuda_runtime.h>
#include <cuda_fp16.h>
#include <cstdint>

#define HW    512
#define NPIX  (HW * HW)          // 262144
#define NC    64
#define CAP   16                 // bucket capacity (Poisson(1): overflow prob ~0)
#define MAXE  64                 // gather-list slots per pixel (9 + pass2<=55; Poisson(9) tail ~0)

// Scratch (__device__ globals per allocation-free rule)
__device__ __half g_refT[(size_t)NPIX * NC];        // ref transposed (pix, C) fp16: 32 MB
__device__ int    g_cnt[NPIX];                      // bucket counts for inverse nnf_rs
__device__ int    g_bucket[CAP][NPIX];              // interleaved: [slot][key] -> ref pixel r
__device__ int    g_list[MAXE][NPIX];               // interleaved gather lists: [slot][pixel]
__device__ int    g_counts[NPIX];                   // m1 | (m2 << 16): pass1 count, pass2 start

// ---------------------------------------------------------------------------
// 1) Transpose + downconvert: ref (C,H,W) fp32 -> refT (H*W, C) fp16.
// ---------------------------------------------------------------------------
__global__ __launch_bounds__(256) void transpose_ref_kernel(const float* __restrict__ ref) {
    __shared__ float tile[64][65];
    const int pixBase = blockIdx.x * 64;
    const int tx = threadIdx.x;   // 0..63
    const int ty = threadIdx.y;   // 0..3

    #pragma unroll
    for (int c = ty; c < NC; c += 4)
        tile[c][tx] = ref[(size_t)c * NPIX + pixBase + tx];   // coalesced over pixels
    __syncthreads();
    #pragma unroll
    for (int p = ty; p < 64; p += 4)
        g_refT[(size_t)(pixBase + p) * NC + tx] = __float2half(tile[tx][p]);
}

// ---------------------------------------------------------------------------
// 2a) Zero bucket counts.
// ---------------------------------------------------------------------------
__global__ __launch_bounds__(256) void zero_cnt_kernel() {
    const int i = blockIdx.x * blockDim.x + threadIdx.x;
    if (i < NPIX) g_cnt[i] = 0;
}

// 2b) Invert nnf_rs: bucket ref pixels r by their target s = nnf_rs[r].
__global__ __launch_bounds__(256) void build_buckets_kernel(const int* __restrict__ nnf_rs) {
    const int r = blockIdx.x * blockDim.x + threadIdx.x;
    if (r >= NPIX) return;
    const int2 nn = ((const int2*)nnf_rs)[r];     // (sy, sx) in [0,512)
    const int key = nn.x * HW + nn.y;
    const int slot = atomicAdd(&g_cnt[key], 1);
    if (slot < CAP) g_bucket[slot][key] = r;
}

// ---------------------------------------------------------------------------
// 3) Precompute gather lists: ONE THREAD PER PIXEL (scalar work done once,
//    not 32x per warp). Pass1 entries fill from front, pass2 from back.
// ---------------------------------------------------------------------------
__global__ __launch_bounds__(256) void precompute_kernel(const int* __restrict__ nnf_sr) {
    const int t = blockIdx.x * blockDim.x + threadIdx.x;
    if (t >= NPIX) return;
    const int ty = t >> 9;
    const int tx = t & (HW - 1);

    int m1 = 0;          // front fill (pass 1)
    int m2 = MAXE;       // back fill (pass 2)

    #pragma unroll
    for (int dy = -1; dy <= 1; dy++) {
        #pragma unroll
        for (int dx = -1; dx <= 1; dx++) {
            const int sy = ty - dy, sx = tx - dx;
            if ((unsigned)sy < HW && (unsigned)sx < HW) {
                const int sidx = sy * HW + sx;

                // pass 1: s -> nnf_sr[s]+d
                const int2 nn = __ldg(&((const int2*)nnf_sr)[sidx]);
                const int qy = nn.x + dy, qx = nn.y + dx;
                if ((unsigned)qy < HW && (unsigned)qx < HW)
                    g_list[m1++][t] = qy * HW + qx;

                // pass 2: bucket entries r with nnf_rs[r] = s, q = r+d
                int n = g_cnt[sidx];
                if (n > CAP) n = CAP;
                for (int i = 0; i < n; i++) {
                    const int r = g_bucket[i][sidx];          // coalesced (interleaved)
                    const int q2y = (r >> 9) + dy, q2x = (r & (HW - 1)) + dx;
                    if (((unsigned)q2y < HW) & ((unsigned)q2x < HW) && m2 > m1)
                        g_list[--m2][t] = q2y * HW + q2x;
                }
            }
        }
    }
    g_counts[t] = m1 | (m2 << 16);
}

// ---------------------------------------------------------------------------
// 4) Vote: one warp per pixel, pure streaming gather + FMA. Broadcast the
//    uniform list entry, coalesced 128B half2 row load, accumulate, then
//    normalize and write (C,H,W) output coalesced via smem transpose.
// ---------------------------------------------------------------------------
__global__ __launch_bounds__(512) void vote_kernel(float* __restrict__ out) {
    __shared__ float s_out[16][65];
    const int warp = threadIdx.x >> 5;            // 0..15 -> pixel within block
    const int lane = threadIdx.x & 31;            // channel pair
    const int pixBase = blockIdx.x * 16;
    const int t = pixBase + warp;

    const int packed = g_counts[t];
    const int m1 = packed & 0xffff;
    const int m2 = packed >> 16;

    const __half2* __restrict__ refT2 = (const __half2*)g_refT;

    float2 a1 = make_float2(0.f, 0.f);
    for (int j = 0; j < m1; j++) {
        const int q = g_list[j][t];                         // uniform broadcast
        const float2 v = __half22float2(__ldg(&refT2[q * 32 + lane]));
        a1.x += v.x; a1.y += v.y;
    }
    float2 a2 = make_float2(0.f, 0.f);
    for (int j = m2; j < MAXE; j++) {
        const int q = g_list[j][t];
        const float2 v = __half22float2(__ldg(&refT2[q * 32 + lane]));
        a2.x += v.x; a2.y += v.y;
    }

    const float ws = 1.0f / (float)NPIX;
    const float wr = 2.0f / (float)NPIX;
    const float w  = ws * (float)m1 + wr * (float)(MAXE - m2);
    const float inv = (w == 0.f) ? 1.f : (1.f / w);
    s_out[warp][2 * lane]     = (ws * a1.x + wr * a2.x) * inv;
    s_out[warp][2 * lane + 1] = (ws * a1.y + wr * a2.y) * inv;
    __syncthreads();

    // Transposed writeout: 512 threads cover 16 pix x 64 ch.
    const int p = threadIdx.x & 15;
    const int c = threadIdx.x >> 4;                   // 0..31
    out[(size_t)c        * NPIX + pixBase + p] = s_out[p][c];
    out[(size_t)(c + 32) * NPIX + pixBase + p] = s_out[p][c + 32];
}

// ---------------------------------------------------------------------------
extern "C" void kernel_launch(void* const* d_in, const int* in_sizes, int n_in,
                              void* d_out, int out_size) {
    const float* ref    = (const float*)d_in[0];
    const int*   nnf_sr = (const int*)d_in[1];
    const int*   nnf_rs = (const int*)d_in[2];
    float*       out    = (float*)d_out;

    dim3 t2d(64, 4);
    transpose_ref_kernel<<<NPIX / 64, t2d>>>(ref);
    zero_cnt_kernel<<<NPIX / 256, 256>>>();
    build_buckets_kernel<<<NPIX / 256, 256>>>(nnf_rs);
    precompute_kernel<<<NPIX / 256, 256>>>(nnf_sr);
    vote_kernel<<<NPIX / 16, 512>>>(out);
}

// round 6
// speedup vs baseline: 1.9938x; 1.0452x over previous
#include <cuda_runtime.h>
#include <cuda_fp16.h>
#include <cstdint>

#define HW    512
#define NPIX  (HW * HW)          // 262144
#define NC    64
#define CAP   16                 // bucket capacity (max Poisson(1) over 262k keys ~ 9-10)
#define MAXE  48                 // list slots/pixel: pass1 [0,9), pass2 [9, 9+n2), n2<=39
#define P2OFF 9                  // fixed start of pass-2 segment (m1 <= 9 always)
#define NQ2   24                 // int2 words per list row (48 ints)

// Scratch (__device__ globals per allocation-free rule)
__device__ __half g_refT[(size_t)NPIX * NC];        // ref transposed (pix, C) fp16: 32 MB
__device__ int    g_cnt[NPIX];                      // bucket counts for inverse nnf_rs
__device__ int    g_bucket[CAP][NPIX];              // interleaved: [slot][key] -> ref pixel r
__device__ int2   g_list[(size_t)NPIX * NQ2];       // pixel-major lists: 48 MB
__device__ int    g_counts[NPIX];                   // m1 | (n2 << 16)

// ---------------------------------------------------------------------------
// 1) Transpose + downconvert: ref (C,H,W) fp32 -> refT (H*W, C) fp16.
// ---------------------------------------------------------------------------
__global__ __launch_bounds__(256) void transpose_ref_kernel(const float* __restrict__ ref) {
    __shared__ float tile[64][65];
    const int pixBase = blockIdx.x * 64;
    const int tx = threadIdx.x;   // 0..63
    const int ty = threadIdx.y;   // 0..3

    #pragma unroll
    for (int c = ty; c < NC; c += 4)
        tile[c][tx] = ref[(size_t)c * NPIX + pixBase + tx];   // coalesced over pixels
    __syncthreads();
    #pragma unroll
    for (int p = ty; p < 64; p += 4)
        g_refT[(size_t)(pixBase + p) * NC + tx] = __float2half(tile[tx][p]);
}

// ---------------------------------------------------------------------------
// 2a) Zero bucket counts.  2b) Invert nnf_rs into buckets.
// ---------------------------------------------------------------------------
__global__ __launch_bounds__(256) void zero_cnt_kernel() {
    const int i = blockIdx.x * blockDim.x + threadIdx.x;
    if (i < NPIX) g_cnt[i] = 0;
}
__global__ __launch_bounds__(256) void build_buckets_kernel(const int* __restrict__ nnf_rs) {
    const int r = blockIdx.x * blockDim.x + threadIdx.x;
    if (r >= NPIX) return;
    const int2 nn = ((const int2*)nnf_rs)[r];     // (sy, sx) in [0,512)
    const int key = nn.x * HW + nn.y;
    const int slot = atomicAdd(&g_cnt[key], 1);
    if (slot < CAP) g_bucket[slot][key] = r;
}

// ---------------------------------------------------------------------------
// 3) Precompute gather lists, one THREAD per pixel. Stage in smem, FIXED
//    segments: pass1 -> [0, m1), pass2 -> [9, 9+n2). No compaction.
// ---------------------------------------------------------------------------
__global__ __launch_bounds__(128) void precompute_kernel(const int* __restrict__ nnf_sr) {
    __shared__ int s_list[128][MAXE + 1];         // +1 pad: bank-conflict-free columns
    const int tid = threadIdx.x;
    const int base = blockIdx.x * 128;
    const int t = base + tid;
    const int ty = t >> 9;
    const int tx = t & (HW - 1);

    int m1 = 0;            // pass1 fill [0, m1), m1 <= 9
    int p2 = P2OFF;        // pass2 fill [9, p2)

    #pragma unroll
    for (int dy = -1; dy <= 1; dy++) {
        #pragma unroll
        for (int dx = -1; dx <= 1; dx++) {
            const int sy = ty - dy, sx = tx - dx;
            if ((unsigned)sy < HW && (unsigned)sx < HW) {
                const int sidx = sy * HW + sx;

                // pass 1: s -> nnf_sr[s]+d
                const int2 nn = __ldg(&((const int2*)nnf_sr)[sidx]);
                const int qy = nn.x + dy, qx = nn.y + dx;
                if ((unsigned)qy < HW && (unsigned)qx < HW)
                    s_list[tid][m1++] = qy * HW + qx;

                // pass 2: bucket entries r with nnf_rs[r] = s, q = r+d
                int n = g_cnt[sidx];
                if (n > CAP) n = CAP;
                for (int i = 0; i < n; i++) {
                    const int r = g_bucket[i][sidx];          // coalesced (interleaved)
                    const int q2y = (r >> 9) + dy, q2x = (r & (HW - 1)) + dx;
                    if (((unsigned)q2y < HW) & ((unsigned)q2x < HW) && p2 < MAXE)
                        s_list[tid][p2++] = q2y * HW + q2x;
                }
            }
        }
    }
    g_counts[t] = m1 | ((p2 - P2OFF) << 16);
    __syncthreads();

    // coalesced copy-out: 4 warps sweep 128 rows; 24 lanes write int2 each
    const int warp = tid >> 5, lane = tid & 31;
    if (lane < NQ2) {
        for (int r = warp; r < 128; r += 4) {
            int2 v = make_int2(s_list[r][2 * lane], s_list[r][2 * lane + 1]);
            g_list[(size_t)(base + r) * NQ2 + lane] = v;
        }
    }
}

// ---------------------------------------------------------------------------
// 4) Vote: one warp per pixel. Whole list register-resident (one LDG.64 +
//    shfl), two gather loops (per segment) unrolled x4, MLP=4.
// ---------------------------------------------------------------------------
__global__ __launch_bounds__(512) void vote_kernel(float* __restrict__ out) {
    __shared__ float s_out[16][65];
    const int warp = threadIdx.x >> 5;            // 0..15 -> pixel within block
    const int lane = threadIdx.x & 31;            // channel pair
    const int pixBase = blockIdx.x * 16;
    const int t = pixBase + warp;

    const int packed = g_counts[t];
    const int m1 = packed & 0xffff;
    const int n2 = packed >> 16;

    int2 myq = make_int2(0, 0);
    if (lane < NQ2) myq = __ldg(&g_list[(size_t)t * NQ2 + lane]);

    const __half2* __restrict__ refT2 = (const __half2*)g_refT;

    float2 a1 = make_float2(0.f, 0.f);
    float2 a2 = make_float2(0.f, 0.f);

    #define GETQ(j) __shfl_sync(0xffffffffu, ((j) & 1) ? myq.y : myq.x, (j) >> 1)

    // --- pass 1 segment [0, m1) ---
    {
        int j = 0;
        for (; j + 4 <= m1; j += 4) {
            const int q0 = GETQ(j), q1 = GETQ(j + 1), q2 = GETQ(j + 2), q3 = GETQ(j + 3);
            const __half2 h0 = __ldg(&refT2[q0 * 32 + lane]);
            const __half2 h1 = __ldg(&refT2[q1 * 32 + lane]);
            const __half2 h2 = __ldg(&refT2[q2 * 32 + lane]);
            const __half2 h3 = __ldg(&refT2[q3 * 32 + lane]);
            const float2 v0 = __half22float2(h0), v1 = __half22float2(h1);
            const float2 v2 = __half22float2(h2), v3 = __half22float2(h3);
            a1.x += v0.x + v1.x + v2.x + v3.x;
            a1.y += v0.y + v1.y + v2.y + v3.y;
        }
        for (; j < m1; j++) {
            const int q = GETQ(j);
            const float2 v = __half22float2(__ldg(&refT2[q * 32 + lane]));
            a1.x += v.x; a1.y += v.y;
        }
    }
    // --- pass 2 segment [P2OFF, P2OFF + n2) ---
    {
        const int end = P2OFF + n2;
        int j = P2OFF;
        for (; j + 4 <= end; j += 4) {
            const int q0 = GETQ(j), q1 = GETQ(j + 1), q2 = GETQ(j + 2), q3 = GETQ(j + 3);
            const __half2 h0 = __ldg(&refT2[q0 * 32 + lane]);
            const __half2 h1 = __ldg(&refT2[q1 * 32 + lane]);
            const __half2 h2 = __ldg(&refT2[q2 * 32 + lane]);
            const __half2 h3 = __ldg(&refT2[q3 * 32 + lane]);
            const float2 v0 = __half22float2(h0), v1 = __half22float2(h1);
            const float2 v2 = __half22float2(h2), v3 = __half22float2(h3);
            a2.x += v0.x + v1.x + v2.x + v3.x;
            a2.y += v0.y + v1.y + v2.y + v3.y;
        }
        for (; j < end; j++) {
            const int q = GETQ(j);
            const float2 v = __half22float2(__ldg(&refT2[q * 32 + lane]));
            a2.x += v.x; a2.y += v.y;
        }
    }
    #undef GETQ

    const float ws = 1.0f / (float)NPIX;
    const float wr = 2.0f / (float)NPIX;
    const float w  = ws * (float)m1 + wr * (float)n2;
    const float inv = (w == 0.f) ? 1.f : (1.f / w);
    s_out[warp][2 * lane]     = (ws * a1.x + wr * a2.x) * inv;
    s_out[warp][2 * lane + 1] = (ws * a1.y + wr * a2.y) * inv;
    __syncthreads();

    // Transposed writeout: 512 threads cover 16 pix x 64 ch.
    const int p = threadIdx.x & 15;
    const int c = threadIdx.x >> 4;                   // 0..31
    out[(size_t)c        * NPIX + pixBase + p] = s_out[p][c];
    out[(size_t)(c + 32) * NPIX + pixBase + p] = s_out[p][c + 32];
}

// ---------------------------------------------------------------------------
extern "C" void kernel_launch(void* const* d_in, const int* in_sizes, int n_in,
                              void* d_out, int out_size) {
    const float* ref    = (const float*)d_in[0];
    const int*   nnf_sr = (const int*)d_in[1];
    const int*   nnf_rs = (const int*)d_in[2];
    float*       out    = (float*)d_out;

    dim3 t2d(64, 4);
    transpose_ref_kernel<<<NPIX / 64, t2d>>>(ref);
    zero_cnt_kernel<<<NPIX / 256, 256>>>();
    build_buckets_kernel<<<NPIX / 256, 256>>>(nnf_rs);
    precompute_kernel<<<NPIX / 128, 128>>>(nnf_sr);
    vote_kernel<<<NPIX / 16, 512>>>(out);
}